// round 11
// baseline (speedup 1.0000x reference)
#include <cuda_runtime.h>
#include <cuda_fp16.h>

#define RDIM 512
#define CDIM 32
#define NPLANE 3
#define PLANE_ELEMS (RDIM * RDIM * CDIM)   // 8,388,608 elems per plane

// 48 MB scratch: clipped triplane as fp16 in [plane][y][x][channel] layout.
// Pixel block = 32 halves = 64 B (2 sectors) -> 768 B/point, the data minimum.
__device__ __half g_planes[NPLANE * PLANE_ELEMS];

// Blackwell packed-f32x2 helpers (ptxas won't auto-fuse these from C++).
#define PACK_F32X2(out, lo, hi) \
    asm("mov.b64 %0, {%1, %2};" : "=l"(out) : "f"(lo), "f"(hi))
#define ADD_F32X2(out, a, b) \
    asm("add.rn.f32x2 %0, %1, %2;" : "=l"(out) : "l"(a), "l"(b))

// ---------------------------------------------------------------------------
// Kernel 1: transpose [p][c][y][x] -> [p][y][x][c], clip to [-1,1], fp32->fp16.
// One block = (p, y, 128-wide x tile); 256 threads.
// __ldcs source reads: pure streaming, keeps the 96MB input out of L2 so the
// fp16 scratch it produces stays resident (measured: ~16us).
// ---------------------------------------------------------------------------
__global__ void __launch_bounds__(256) transpose_clip_kernel(
    const float* __restrict__ src)
{
    __shared__ float tile[CDIM][128];

    int bid   = blockIdx.x;
    int xbase = (bid & 3) << 7;        // 4 x-tiles of 128
    int y     = (bid >> 2) & (RDIM - 1);
    int p     = bid >> 11;             // 4 * 512 = 2048 blocks per plane

    int t = threadIdx.x;

    const float* s = src + (size_t)(p * CDIM) * (RDIM * RDIM) + y * RDIM + xbase;
    #pragma unroll
    for (int i = 0; i < 4; i++) {
        int idx = t + i * 256;
        int c   = idx >> 5;
        int xq  = idx & 31;                       // float4 within row
        float4 f = __ldcs(reinterpret_cast<const float4*>(s + c * (RDIM * RDIM)) + xq);
        int col = (xq * 4) ^ (4 * ((c >> 3) & 3));  // xor swizzle (16B aligned)
        *reinterpret_cast<float4*>(&tile[c][col]) = f;
    }
    __syncthreads();

    __half* d = g_planes + ((size_t)(p * RDIM + y) * RDIM + xbase) * CDIM;
    #pragma unroll
    for (int i = 0; i < 2; i++) {
        int idx = t + i * 256;
        int x   = idx >> 2;            // pixel within tile
        int cq  = idx & 3;             // 8-channel group
        __half h[8];
        #pragma unroll
        for (int k = 0; k < 8; k++) {
            int c = cq * 8 + k;
            float v = tile[c][x ^ (4 * cq)];   // (c>>3)&3 == cq
            v = fminf(fmaxf(v, -1.0f), 1.0f);
            h[k] = __float2half_rn(v);
        }
        reinterpret_cast<uint4*>(d)[idx] = *reinterpret_cast<uint4*>(h);
    }
}

// ---------------------------------------------------------------------------
// Kernel 2: bilinear sampling, 4 lanes per point (proven R6 shape, 78.5us).
// Lane g owns 8 fp16 channels (one 16B slice); 4 __ldg tap loads per plane
// (default caching — triplane MUST stay L2-resident; .cs here costs 10us).
// HFMA2 tap combine; cross-plane accumulate in packed f32x2.
// Output via __stcs: the 128MB write stream has zero reuse; evict-first
// protects the triplane's L2 residency.
// Plane (u=col, v=row) from inv(PLANE_AXES): p0:(cy,cx) p1:(cz,cx) p2:(cy,cz)
// ---------------------------------------------------------------------------
__global__ void __launch_bounds__(256, 6) sample_kernel(
    const float* __restrict__ coords, float* __restrict__ out, int M)
{
    int tid = blockIdx.x * blockDim.x + threadIdx.x;
    int pt  = tid >> 2;
    if (pt >= M) return;
    int g   = tid & 3;

    float cx = __ldg(coords + pt * 3 + 0);
    float cy = __ldg(coords + pt * 3 + 1);
    float cz = __ldg(coords + pt * 3 + 2);

    const uint4* pl = reinterpret_cast<const uint4*>(g_planes);

    float u[3] = {cy, cz, cy};   // -> x (column)
    float v[3] = {cx, cx, cz};   // -> y (row)

    unsigned long long acc[4];   // 4 packed f32x2 = 8 fp32 channels
    #pragma unroll
    for (int j = 0; j < 4; j++) acc[j] = 0ULL;

    #pragma unroll
    for (int p = 0; p < NPLANE; p++) {
        // align_corners=True: sx = (u+1)*0.5*(R-1) = u*255.5 + 255.5, in [0,511)
        float sx = fmaf(u[p], 255.5f, 255.5f);
        float sy = fmaf(v[p], 255.5f, 255.5f);
        int x0 = min(__float2int_rd(sx), RDIM - 2);
        int y0 = min(__float2int_rd(sy), RDIM - 2);
        float wx1 = sx - (float)x0;
        float wy1 = sy - (float)y0;
        float wx0 = 1.0f - wx1, wy0 = 1.0f - wy1;

        __half2 W00 = __float2half2_rn(wx0 * wy0);
        __half2 W10 = __float2half2_rn(wx1 * wy0);
        __half2 W01 = __float2half2_rn(wx0 * wy1);
        __half2 W11 = __float2half2_rn(wx1 * wy1);

        // 32-bit offset addressing from a single base (uint4 units).
        int off = p * (RDIM * RDIM * 4) + y0 * (RDIM * 4) + x0 * 4 + g;
        uint4 q00 = __ldg(pl + off);
        uint4 q10 = __ldg(pl + off + 4);              // x0+1
        uint4 q01 = __ldg(pl + off + RDIM * 4);       // y0+1
        uint4 q11 = __ldg(pl + off + RDIM * 4 + 4);

        const __half2* h00 = reinterpret_cast<const __half2*>(&q00);
        const __half2* h10 = reinterpret_cast<const __half2*>(&q10);
        const __half2* h01 = reinterpret_cast<const __half2*>(&q01);
        const __half2* h11 = reinterpret_cast<const __half2*>(&q11);

        #pragma unroll
        for (int j = 0; j < 4; j++) {
            __half2 s = __hmul2(W00, h00[j]);
            s = __hfma2(W10, h10[j], s);
            s = __hfma2(W01, h01[j], s);
            s = __hfma2(W11, h11[j], s);
            float2 f = __half22float2(s);      // fp32 across planes
            unsigned long long pf;
            PACK_F32X2(pf, f.x, f.y);
            ADD_F32X2(acc[j], acc[j], pf);
        }
    }

    // Lane g writes channels [8g, 8g+8): two streaming STG.128 directly from
    // the packed f32x2 register pairs; warp covers full 128B lines.
    ulonglong2* o = reinterpret_cast<ulonglong2*>(out) + pt * (CDIM / 4) + g * 2;
    __stcs(o,     make_ulonglong2(acc[0], acc[1]));
    __stcs(o + 1, make_ulonglong2(acc[2], acc[3]));
}

// ---------------------------------------------------------------------------
extern "C" void kernel_launch(void* const* d_in, const int* in_sizes, int n_in,
                              void* d_out, int out_size) {
    const float* coords   = (const float*)d_in[0];
    const float* triplane = (const float*)d_in[1];
    float*       out      = (float*)d_out;
    int M = in_sizes[0] / 3;

    transpose_clip_kernel<<<NPLANE * RDIM * (RDIM / 128), 256>>>(triplane);

    long long threads = (long long)M * 4;
    sample_kernel<<<(int)((threads + 255) / 256), 256>>>(coords, out, M);
}

// round 13
// speedup vs baseline: 1.6057x; 1.6057x over previous
#include <cuda_runtime.h>
#include <cuda_fp16.h>

#define RDIM 512
#define CDIM 32
#define NPLANE 3
#define PLANE_ELEMS (RDIM * RDIM * CDIM)   // 8,388,608 elems per plane

// 48 MB scratch: clipped triplane as fp16 in [plane][y][x][channel] layout.
// Pixel block = 32 halves = 64 B (2 sectors) -> 768 B/point, the data minimum.
__device__ __half g_planes[NPLANE * PLANE_ELEMS];

// Blackwell packed-f32x2 helpers (ptxas won't auto-fuse these from C++).
#define PACK_F32X2(out, lo, hi) \
    asm("mov.b64 %0, {%1, %2};" : "=l"(out) : "f"(lo), "f"(hi))
#define UNPACK_F32X2(lo, hi, in) \
    asm("mov.b64 {%0, %1}, %2;" : "=f"(lo), "=f"(hi) : "l"(in))
#define ADD_F32X2(out, a, b) \
    asm("add.rn.f32x2 %0, %1, %2;" : "=l"(out) : "l"(a), "l"(b))

// ---------------------------------------------------------------------------
// Kernel 1: transpose [p][c][y][x] -> [p][y][x][c], clip to [-1,1], fp32->fp16.
// One block = (p, y, 128-wide x tile); 256 threads.
// __ldcs source reads: pure streaming — keeps the 96MB fp32 input out of L2
// so the fp16 scratch written here stays resident (measured ~16us in R10).
// Scratch writes use DEFAULT policy (they must become L2-resident).
// ---------------------------------------------------------------------------
__global__ void __launch_bounds__(256) transpose_clip_kernel(
    const float* __restrict__ src)
{
    __shared__ float tile[CDIM][128];

    int bid   = blockIdx.x;
    int xbase = (bid & 3) << 7;        // 4 x-tiles of 128
    int y     = (bid >> 2) & (RDIM - 1);
    int p     = bid >> 11;             // 4 * 512 = 2048 blocks per plane

    int t = threadIdx.x;

    const float* s = src + (size_t)(p * CDIM) * (RDIM * RDIM) + y * RDIM + xbase;
    #pragma unroll
    for (int i = 0; i < 4; i++) {
        int idx = t + i * 256;
        int c   = idx >> 5;
        int xq  = idx & 31;                       // float4 within row
        float4 f = __ldcs(reinterpret_cast<const float4*>(s + c * (RDIM * RDIM)) + xq);
        int col = (xq * 4) ^ (4 * ((c >> 3) & 3));  // xor swizzle (16B aligned)
        *reinterpret_cast<float4*>(&tile[c][col]) = f;
    }
    __syncthreads();

    __half* d = g_planes + ((size_t)(p * RDIM + y) * RDIM + xbase) * CDIM;
    #pragma unroll
    for (int i = 0; i < 2; i++) {
        int idx = t + i * 256;
        int x   = idx >> 2;            // pixel within tile
        int cq  = idx & 3;             // 8-channel group
        __half h[8];
        #pragma unroll
        for (int k = 0; k < 8; k++) {
            int c = cq * 8 + k;
            float v = tile[c][x ^ (4 * cq)];   // (c>>3)&3 == cq
            v = fminf(fmaxf(v, -1.0f), 1.0f);
            h[k] = __float2half_rn(v);
        }
        reinterpret_cast<uint4*>(d)[idx] = *reinterpret_cast<uint4*>(h);
    }
}

// ---------------------------------------------------------------------------
// Kernel 2: bilinear sampling — R6 shape verbatim (measured 78.5us).
// 4 lanes per point; lane g owns 8 fp16 channels (one 16B slice).
// DEFAULT-policy __ldg taps (L2 residency is everything: .cs reads cost +10us)
// and DEFAULT-policy float4 stores (.cs stores cost +44us — slow STG path).
// HFMA2 tap combine; cross-plane accumulate in packed add.rn.f32x2.
// Plane (u=col, v=row) from inv(PLANE_AXES): p0:(cy,cx) p1:(cz,cx) p2:(cy,cz)
// ---------------------------------------------------------------------------
__global__ void __launch_bounds__(256, 6) sample_kernel(
    const float* __restrict__ coords, float* __restrict__ out, int M)
{
    int tid = blockIdx.x * blockDim.x + threadIdx.x;
    int pt  = tid >> 2;
    if (pt >= M) return;
    int g   = tid & 3;

    float cx = __ldg(coords + pt * 3 + 0);
    float cy = __ldg(coords + pt * 3 + 1);
    float cz = __ldg(coords + pt * 3 + 2);

    const uint4* pl = reinterpret_cast<const uint4*>(g_planes);

    float u[3] = {cy, cz, cy};   // -> x (column)
    float v[3] = {cx, cx, cz};   // -> y (row)

    unsigned long long acc[4];   // 4 packed f32x2 = 8 fp32 channels
    #pragma unroll
    for (int j = 0; j < 4; j++) acc[j] = 0ULL;   // bits of (+0.f, +0.f)

    #pragma unroll
    for (int p = 0; p < NPLANE; p++) {
        // align_corners=True: sx = (u+1)*0.5*(R-1) = u*255.5 + 255.5, in [0,511)
        float sx = fmaf(u[p], 255.5f, 255.5f);
        float sy = fmaf(v[p], 255.5f, 255.5f);
        int x0 = min(__float2int_rd(sx), RDIM - 2);
        int y0 = min(__float2int_rd(sy), RDIM - 2);
        float wx1 = sx - (float)x0;
        float wy1 = sy - (float)y0;
        float wx0 = 1.0f - wx1, wy0 = 1.0f - wy1;

        __half2 W00 = __float2half2_rn(wx0 * wy0);
        __half2 W10 = __float2half2_rn(wx1 * wy0);
        __half2 W01 = __float2half2_rn(wx0 * wy1);
        __half2 W11 = __float2half2_rn(wx1 * wy1);

        const uint4* r = pl + p * (RDIM * RDIM * 4) + y0 * (RDIM * 4) + x0 * 4 + g;
        uint4 q00 = __ldg(r);
        uint4 q10 = __ldg(r + 4);              // x0+1
        uint4 q01 = __ldg(r + RDIM * 4);       // y0+1
        uint4 q11 = __ldg(r + RDIM * 4 + 4);

        const __half2* h00 = reinterpret_cast<const __half2*>(&q00);
        const __half2* h10 = reinterpret_cast<const __half2*>(&q10);
        const __half2* h01 = reinterpret_cast<const __half2*>(&q01);
        const __half2* h11 = reinterpret_cast<const __half2*>(&q11);

        #pragma unroll
        for (int j = 0; j < 4; j++) {
            __half2 s = __hmul2(W00, h00[j]);
            s = __hfma2(W10, h10[j], s);
            s = __hfma2(W01, h01[j], s);
            s = __hfma2(W11, h11[j], s);
            float2 f = __half22float2(s);      // fp32 across planes
            unsigned long long pf;
            PACK_F32X2(pf, f.x, f.y);
            ADD_F32X2(acc[j], acc[j], pf);
        }
    }

    float a0, a1, a2, a3, a4, a5, a6, a7;
    UNPACK_F32X2(a0, a1, acc[0]);
    UNPACK_F32X2(a2, a3, acc[1]);
    UNPACK_F32X2(a4, a5, acc[2]);
    UNPACK_F32X2(a6, a7, acc[3]);

    // Lane g writes channels [8g, 8g+8): two default-policy STG.128;
    // warp covers full 128B lines.
    float4* o = reinterpret_cast<float4*>(out) + pt * (CDIM / 4) + g * 2;
    o[0] = make_float4(a0, a1, a2, a3);
    o[1] = make_float4(a4, a5, a6, a7);
}

// ---------------------------------------------------------------------------
extern "C" void kernel_launch(void* const* d_in, const int* in_sizes, int n_in,
                              void* d_out, int out_size) {
    const float* coords   = (const float*)d_in[0];
    const float* triplane = (const float*)d_in[1];
    float*       out      = (float*)d_out;
    int M = in_sizes[0] / 3;

    transpose_clip_kernel<<<NPLANE * RDIM * (RDIM / 128), 256>>>(triplane);

    long long threads = (long long)M * 4;
    sample_kernel<<<(int)((threads + 255) / 256), 256>>>(coords, out, M);
}